// round 13
// baseline (speedup 1.0000x reference)
#include <cuda_runtime.h>
#include <math.h>

#define FRAMES 2048
#define BEPS 1e-5f

typedef unsigned long long ull;

// ---------------- scratch ----------------
__device__ __align__(16) float g_y1[FRAMES * 16 * 144];   // [2048,16,12,12]
__device__ float g_c[FRAMES];
__device__ int   g_p[32];
__device__ int   g_chain[6][32];
__device__ int   g_chain_len[6];

__device__ __forceinline__ float fast_tanh(float x) {
    return 1.0f - 2.0f / (1.0f + __expf(2.0f * x));
}
__device__ __forceinline__ float tanhap(float x) {
    float y;
    asm("tanh.approx.f32 %0, %1;" : "=f"(y) : "f"(x));
    return y;
}
__device__ __forceinline__ float sigap(float x) {
    return fmaf(0.5f, tanhap(0.5f * x), 0.5f);
}
__device__ __forceinline__ ull fma2(ull a, ull b, ull c) {
    ull d;
    asm("fma.rn.f32x2 %0, %1, %2, %3;" : "=l"(d) : "l"(a), "l"(b), "l"(c));
    return d;
}
__device__ __forceinline__ ull add2(ull a, ull b) {
    ull d;
    asm("add.rn.f32x2 %0, %1, %2;" : "=l"(d) : "l"(a), "l"(b));
    return d;
}
__device__ __forceinline__ float lo2(ull a) { return __uint_as_float((unsigned)(a & 0xffffffffu)); }
__device__ __forceinline__ float hi2(ull a) { return __uint_as_float((unsigned)(a >> 32)); }
__device__ __forceinline__ float acc4(float acc, float4 a, float4 b) {
    acc = fmaf(a.x, b.x, acc);
    acc = fmaf(a.y, b.y, acc);
    acc = fmaf(a.z, b.z, acc);
    acc = fmaf(a.w, b.w, acc);
    return acc;
}

// ---------------- Kernel A: conv1 + bias + BN + ReLU + 3x3/3 maxpool ----------
__global__ void __launch_bounds__(128) conv1_kernel(
    const float* __restrict__ x,
    const float* __restrict__ w,        // [16,3,4,4]
    const float* __restrict__ bias,
    const float* __restrict__ bg, const float* __restrict__ bb,
    const float* __restrict__ bm, const float* __restrict__ bv)
{
    __shared__ float4 smem[1296];       // 3*12*36 float4 patch (20736 B)
    __shared__ float4 swt[192];         // 16ch * 12 float4 weights (3072 B)
    __shared__ float  sconv[9 * 12 * 16];  // sub-conv results (6912 B)

    const int f  = blockIdx.x;
    const int py = blockIdx.y;
    const int tid = threadIdx.x;

    const float4* xin = (const float4*)x;
    const long base = (long)f * 15552 + (long)py * 432;   // f4 units
    const unsigned sb_p = (unsigned)__cvta_generic_to_shared(smem);
    const unsigned sb_w = (unsigned)__cvta_generic_to_shared(swt);

    #pragma unroll
    for (int j = 0; j < 10; j++) {
        const int i = tid + j * 128;
        const int ic = i / 432;
        asm volatile("cp.async.cg.shared.global [%0], [%1], 16;\n"
                     :: "r"(sb_p + i * 16), "l"(xin + base + i + ic * 4752));
    }
    if (tid < 16) {
        const int i = 1280 + tid;       // ic == 2
        asm volatile("cp.async.cg.shared.global [%0], [%1], 16;\n"
                     :: "r"(sb_p + i * 16), "l"(xin + base + i + 2 * 4752));
    }
    {
        const float4* wg = (const float4*)w;
        asm volatile("cp.async.cg.shared.global [%0], [%1], 16;\n"
                     :: "r"(sb_w + tid * 16), "l"(wg + tid));
        if (tid < 64)
            asm volatile("cp.async.cg.shared.global [%0], [%1], 16;\n"
                         :: "r"(sb_w + (128 + tid) * 16), "l"(wg + 128 + tid));
    }
    asm volatile("cp.async.commit_group;\n");
    asm volatile("cp.async.wait_group 0;\n");
    __syncthreads();

    if (tid < 108) {
        const int px = tid % 12;
        const int s9 = tid / 12;        // sy*3+sx
        const int sy = s9 / 3, sx = s9 - sy * 3;

        ulonglong2 xr[12];
        #pragma unroll
        for (int ic = 0; ic < 3; ic++)
            #pragma unroll
            for (int ky = 0; ky < 4; ky++)
                xr[ic * 4 + ky] = *(const ulonglong2*)
                    &smem[(ic * 12 + sy * 4 + ky) * 36 + px * 3 + sx];

        #pragma unroll
        for (int ch = 0; ch < 16; ch++) {
            const ulonglong2* wch = (const ulonglong2*)(swt + ch * 12);
            ull A = 0, B = 0;
            #pragma unroll
            for (int r = 0; r < 12; r++) {
                const ulonglong2 wr = wch[r];     // broadcast (same addr)
                A = fma2(xr[r].x, wr.x, A);
                B = fma2(xr[r].y, wr.y, B);
            }
            const ull S = add2(A, B);
            sconv[(s9 * 12 + px) * 16 + ch] = lo2(S) + hi2(S);
        }
    }
    __syncthreads();

    {
        const int o = tid;
        const int px = o >> 4, ch = o & 15;
        const float scale = bg[ch] * rsqrtf(bv[ch] + BEPS);
        const float shift2 = bb[ch] - bm[ch] * scale + bias[ch] * scale;
        float m = -1e30f;
        #pragma unroll
        for (int s9 = 0; s9 < 9; s9++)
            m = fmaxf(m, fmaxf(fmaf(sconv[(s9 * 12 + px) * 16 + ch], scale, shift2), 0.0f));
        g_y1[((f * 16 + ch) * 12 + py) * 12 + px] = m;
    }
    if (tid < 64) {
        const int o = 128 + tid;
        const int px = o >> 4, ch = o & 15;
        const float scale = bg[ch] * rsqrtf(bv[ch] + BEPS);
        const float shift2 = bb[ch] - bm[ch] * scale + bias[ch] * scale;
        float m = -1e30f;
        #pragma unroll
        for (int s9 = 0; s9 < 9; s9++)
            m = fmaxf(m, fmaxf(fmaf(sconv[(s9 * 12 + px) * 16 + ch], scale, shift2), 0.0f));
        g_y1[((f * 16 + ch) * 12 + py) * 12 + px] = m;
    }
}

// ---------------- Kernel B: conv2 -> scalar per frame ------------------------
__global__ void __launch_bounds__(256) conv2_kernel(
    const float* __restrict__ w2, const float* __restrict__ b2p,
    const float* __restrict__ bg, const float* __restrict__ bb,
    const float* __restrict__ bm, const float* __restrict__ bv)
{
    const int f = blockIdx.x * 8 + (threadIdx.x >> 5);
    const int lane = threadIdx.x & 31;
    const int ch = lane & 15, half = lane >> 4;

    const float4* wf4 = (const float4*)w2;
    const float4 wa = wf4[ch * 4 + half * 2 + 0];
    const float4 wb = wf4[ch * 4 + half * 2 + 1];

    const float scale = bg[0] * rsqrtf(bv[0] + BEPS);
    const float shift = bb[0] - bm[0] * scale;
    const float cb = b2p[0];

    const float4* y4 = (const float4*)g_y1;
    const long cbase = ((long)f * 16 + ch) * 36;

    float best = -1e30f;
    #pragma unroll
    for (int sy = 0; sy < 3; sy++) {
        #pragma unroll
        for (int sx = 0; sx < 3; sx++) {
            int ky0 = half * 2;
            float4 va = y4[cbase + (sy * 4 + ky0) * 3 + sx];
            float4 vb = y4[cbase + (sy * 4 + ky0 + 1) * 3 + sx];
            float acc = acc4(acc4(0.0f, va, wa), vb, wb);
            #pragma unroll
            for (int off = 16; off; off >>= 1)
                acc += __shfl_xor_sync(0xffffffffu, acc, off);
            float val = fmaxf(fmaf(acc + cb, scale, shift), 0.0f);
            best = fmaxf(best, val);
        }
    }
    if (lane == 0) g_c[f] = best;
}

// ---------------- Kernel C: gating MLP + argmax + chain build ----------------
__global__ void __launch_bounds__(1024) gate_kernel(
    const float* __restrict__ w1, const float* __restrict__ b1,
    const float* __restrict__ w2, const float* __restrict__ b2,
    const float* __restrict__ w3, const float* __restrict__ b3)
{
    __shared__ float sc[32][65];
    __shared__ float sh1[32][33];
    __shared__ float sh2[32][33];
    __shared__ float sw1[2048];
    __shared__ float sw2[1024];
    const int tid = threadIdx.x;
    const int s = tid >> 5, j = tid & 31;

    for (int i = tid; i < 2048; i += 1024) {
        sc[i >> 6][i & 63] = g_c[i];
        sw1[i] = w1[i];
    }
    if (tid < 1024) sw2[tid] = w2[tid];
    __syncthreads();

    {
        float acc = b1[j];
        #pragma unroll 8
        for (int t = 0; t < 64; t++) acc = fmaf(sc[s][t], sw1[j * 64 + t], acc);
        sh1[s][j] = fast_tanh(acc);
    }
    __syncthreads();
    {
        float acc = b2[j];
        #pragma unroll
        for (int t = 0; t < 32; t++) acc = fmaf(sh1[s][t], sw2[j * 32 + t], acc);
        sh2[s][j] = fast_tanh(acc);
    }
    __syncthreads();

    if (tid < 32) {
        float bestv = -1e30f; int besti = 0;
        #pragma unroll
        for (int a = 0; a < 6; a++) {
            float acc = b3[a];
            #pragma unroll
            for (int t = 0; t < 32; t++) acc = fmaf(sh2[tid][t], w3[a * 32 + t], acc);
            if (acc > bestv) { bestv = acc; besti = a; }
        }
        g_p[tid] = besti;
    }
    __syncthreads();

    if (tid == 0) {
        int cnt[6] = {0, 0, 0, 0, 0, 0};
        for (int b = 0; b < 32; b++) {
            int e = g_p[b];
            g_chain[e][cnt[e]++] = b;
        }
        for (int e = 0; e < 6; e++) g_chain_len[e] = cnt[e];
    }
}

// ---------------- Kernel D: 4-warp per-expert LSTM + output head -------------
// Warp w computes gate w. Dot = 16 broadcast LDS.64 + 16 fma2 (f32x2 pairs).
// h kept redundantly per-warp in a PRIVATE smem buffer (broadcast reads,
// syncwarp-only visibility). One __syncthreads per step (act exchange).
__global__ void __launch_bounds__(128) lstm_kernel(
    const float* __restrict__ wih,   // [6,128,1]
    const float* __restrict__ whh,   // [6,128,32]
    const float* __restrict__ bih,   // [6,128]
    const float* __restrict__ bhh,   // [6,128]
    const float* __restrict__ hn0,   // [6,32]
    const float* __restrict__ outw,  // [6,64]
    const float* __restrict__ outb,  // [6]
    float* __restrict__ out)         // [32,6]
{
    const int e = blockIdx.x;
    const int tid = threadIdx.x;
    const int w = tid >> 5;          // gate index (0=i,1=f,2=g,3=o)
    const int k = tid & 31;          // hidden unit
    const int len = g_chain_len[e];
    if (len == 0) return;

    const int row = 32 * w + k;
    // weights as 16 natural f32x2 pairs (row contiguous)
    ull W2[16];
    {
        const ull* wr = (const ull*)(whh + (long)e * 4096 + (long)row * 32);
        #pragma unroll
        for (int j = 0; j < 16; j++) W2[j] = wr[j];
    }
    const float wx   = wih[e * 128 + row];
    const float bsum = bih[e * 128 + row] + bhh[e * 128 + row];
    const bool  isg  = (w == 2);

    float h = hn0[e * 32 + k];

    __shared__ ull    shh[4][16];    // per-warp private h copy (pairs)
    __shared__ float4 actb[2][32];   // [buf][k] = (i,f,g,o)
    __shared__ float  scx[64];
    __shared__ float  sr[64];

    ((float*)shh[w])[k] = h;
    __syncwarp();

    for (int s = 0; s < len; s++) {
        const int b = g_chain[e][s];
        if (w == 0) {
            scx[k]      = g_c[b * 64 + k];
            scx[k + 32] = g_c[b * 64 + 32 + k];
        }
        float cst = 0.0f;
        __syncthreads();

        #pragma unroll 2
        for (int t = 0; t < 64; t++) {
            // ---- gate dot: 16 broadcast LDS.64 + 16 fma2, 4 shallow chains ----
            const float xt = scx[t];
            ull A0 = 0, A1 = 0, A2 = 0, A3 = 0;
            #pragma unroll
            for (int m = 0; m < 4; m++) {
                const ull h0 = shh[w][4 * m + 0];
                const ull h1 = shh[w][4 * m + 1];
                const ull h2 = shh[w][4 * m + 2];
                const ull h3 = shh[w][4 * m + 3];
                A0 = fma2(W2[4 * m + 0], h0, A0);
                A1 = fma2(W2[4 * m + 1], h1, A1);
                A2 = fma2(W2[4 * m + 2], h2, A2);
                A3 = fma2(W2[4 * m + 3], h3, A3);
            }
            const ull A = add2(add2(A0, A1), add2(A2, A3));
            const float a = (lo2(A) + hi2(A)) + fmaf(wx, xt, bsum);
            const float act = isg ? tanhap(a) : sigap(a);
            ((float*)(&actb[t & 1][k]))[w] = act;
            __syncthreads();

            // ---- elementwise (redundant in all warps) ----
            const float4 g4 = actb[t & 1][k];
            cst = fmaf(g4.y, cst, g4.x * g4.z);
            h = g4.w * tanhap(cst);
            ((float*)shh[w])[k] = h;
            if (w == 0 && k == 31) sr[t] = h;
            __syncwarp();
        }

        if (w == 0) {
            if (k < 6) {
                float acc = outb[k];
                #pragma unroll 8
                for (int t = 0; t < 64; t++) acc = fmaf(sr[t], outw[k * 64 + t], acc);
                out[b * 6 + k] = acc;
            }
        }
    }
}

// ---------------- launch ----------------
extern "C" void kernel_launch(void* const* d_in, const int* in_sizes, int n_in,
                              void* d_out, int out_size)
{
    const float* x       = (const float*)d_in[0];
    const float* conv1_w = (const float*)d_in[1];
    const float* conv1_b = (const float*)d_in[2];
    const float* bn1_g   = (const float*)d_in[3];
    const float* bn1_b   = (const float*)d_in[4];
    const float* bn1_m   = (const float*)d_in[5];
    const float* bn1_v   = (const float*)d_in[6];
    const float* conv2_w = (const float*)d_in[7];
    const float* conv2_b = (const float*)d_in[8];
    const float* bn2_g   = (const float*)d_in[9];
    const float* bn2_b   = (const float*)d_in[10];
    const float* bn2_m   = (const float*)d_in[11];
    const float* bn2_v   = (const float*)d_in[12];
    const float* pre_w1  = (const float*)d_in[13];
    const float* pre_b1  = (const float*)d_in[14];
    const float* pre_w2  = (const float*)d_in[15];
    const float* pre_b2  = (const float*)d_in[16];
    const float* pre_w3  = (const float*)d_in[17];
    const float* pre_b3  = (const float*)d_in[18];
    const float* lstm_wih = (const float*)d_in[19];
    const float* lstm_whh = (const float*)d_in[20];
    const float* lstm_bih = (const float*)d_in[21];
    const float* lstm_bhh = (const float*)d_in[22];
    const float* hn0     = (const float*)d_in[23];
    const float* out_w   = (const float*)d_in[24];
    const float* out_b   = (const float*)d_in[25];
    float* out = (float*)d_out;

    dim3 gridA(FRAMES, 12);
    conv1_kernel<<<gridA, 128>>>(x, conv1_w, conv1_b, bn1_g, bn1_b, bn1_m, bn1_v);
    conv2_kernel<<<FRAMES / 8, 256>>>(conv2_w, conv2_b, bn2_g, bn2_b, bn2_m, bn2_v);
    gate_kernel<<<1, 1024>>>(pre_w1, pre_b1, pre_w2, pre_b2, pre_w3, pre_b3);
    lstm_kernel<<<6, 128>>>(lstm_wih, lstm_whh, lstm_bih, lstm_bhh, hn0, out_w, out_b, out);
}

// round 15
// speedup vs baseline: 1.1150x; 1.1150x over previous
#include <cuda_runtime.h>
#include <math.h>

#define FRAMES 2048
#define BEPS 1e-5f
#define C1_TILES (FRAMES * 12)
#define C1_GRID 592

typedef unsigned long long ull;

// ---------------- scratch ----------------
__device__ __align__(16) float g_y1[FRAMES * 16 * 144];   // [2048,16,12,12]
__device__ float g_c[FRAMES];
__device__ int   g_p[32];
__device__ int   g_chain[6][32];
__device__ int   g_chain_len[6];

__device__ __forceinline__ float fast_tanh(float x) {
    return 1.0f - 2.0f / (1.0f + __expf(2.0f * x));
}
__device__ __forceinline__ float tanhap(float x) {
    float y;
    asm("tanh.approx.f32 %0, %1;" : "=f"(y) : "f"(x));
    return y;
}
__device__ __forceinline__ float sigap(float x) {
    return fmaf(0.5f, tanhap(0.5f * x), 0.5f);
}
__device__ __forceinline__ ull fma2(ull a, ull b, ull c) {
    ull d;
    asm("fma.rn.f32x2 %0, %1, %2, %3;" : "=l"(d) : "l"(a), "l"(b), "l"(c));
    return d;
}
__device__ __forceinline__ ull add2(ull a, ull b) {
    ull d;
    asm("add.rn.f32x2 %0, %1, %2;" : "=l"(d) : "l"(a), "l"(b));
    return d;
}
__device__ __forceinline__ float lo2(ull a) { return __uint_as_float((unsigned)(a & 0xffffffffu)); }
__device__ __forceinline__ float hi2(ull a) { return __uint_as_float((unsigned)(a >> 32)); }
__device__ __forceinline__ float acc4(float acc, float4 a, float4 b) {
    acc = fmaf(a.x, b.x, acc);
    acc = fmaf(a.y, b.y, acc);
    acc = fmaf(a.z, b.z, acc);
    acc = fmaf(a.w, b.w, acc);
    return acc;
}

// ---------------- Kernel A: conv1 — persistent, double-buffered cp.async ------
// 592 CTAs x 128 threads; each CTA loops over ~41 (frame,pooled-row) tiles.
// Per tile: compute phase = 108 (px,sy,sx) sub-convs with register x-patch and
// broadcast weights; pooling phase folds bias+BN affine (pre-max).
__global__ void __launch_bounds__(128) conv1_kernel(
    const float* __restrict__ x,
    const float* __restrict__ w,        // [16,3,4,4]
    const float* __restrict__ bias,
    const float* __restrict__ bg, const float* __restrict__ bb,
    const float* __restrict__ bm, const float* __restrict__ bv)
{
    extern __shared__ __align__(16) float4 dsm[];
    float4* patch[2] = { dsm, dsm + 1296 };          // 2 x 20736 B
    float4* swt = dsm + 2592;                        // 192 f4 = 3072 B
    float*  sconv = (float*)(dsm + 2784);            // 1728 floats = 6912 B

    const int tid = threadIdx.x;
    const float4* xin = (const float4*)x;

    // per-thread pooling constants (both outputs share ch = tid & 15)
    const int ch_p = tid & 15;
    const float scale = bg[ch_p] * rsqrtf(bv[ch_p] + BEPS);
    const float shift2 = bb[ch_p] - bm[ch_p] * scale + bias[ch_p] * scale;

    // ---- prologue: weights + first tile into patch[0], one group ----
    int tile = blockIdx.x;
    {
        const unsigned sb_w = (unsigned)__cvta_generic_to_shared(swt);
        const float4* wg = (const float4*)w;
        asm volatile("cp.async.cg.shared.global [%0], [%1], 16;\n"
                     :: "r"(sb_w + tid * 16), "l"(wg + tid));
        if (tid < 64)
            asm volatile("cp.async.cg.shared.global [%0], [%1], 16;\n"
                         :: "r"(sb_w + (128 + tid) * 16), "l"(wg + 128 + tid));
        if (tile < C1_TILES) {
            const int f = tile / 12, py = tile - f * 12;
            const long base = (long)f * 15552 + (long)py * 432;
            const unsigned sb = (unsigned)__cvta_generic_to_shared(patch[0]);
            #pragma unroll
            for (int j = 0; j < 10; j++) {
                const int i = tid + j * 128;
                const int ic = i / 432;
                asm volatile("cp.async.cg.shared.global [%0], [%1], 16;\n"
                             :: "r"(sb + i * 16), "l"(xin + base + i + ic * 4752));
            }
            if (tid < 16) {
                const int i = 1280 + tid;
                asm volatile("cp.async.cg.shared.global [%0], [%1], 16;\n"
                             :: "r"(sb + i * 16), "l"(xin + base + i + 2 * 4752));
            }
        }
        asm volatile("cp.async.commit_group;\n");
    }

    int cur = 0;
    for (; tile < C1_TILES; tile += C1_GRID, cur ^= 1) {
        // ---- prefetch next tile into the other buffer ----
        const int nxt = tile + C1_GRID;
        if (nxt < C1_TILES) {
            const int f = nxt / 12, py = nxt - f * 12;
            const long base = (long)f * 15552 + (long)py * 432;
            const unsigned sb = (unsigned)__cvta_generic_to_shared(patch[cur ^ 1]);
            #pragma unroll
            for (int j = 0; j < 10; j++) {
                const int i = tid + j * 128;
                const int ic = i / 432;
                asm volatile("cp.async.cg.shared.global [%0], [%1], 16;\n"
                             :: "r"(sb + i * 16), "l"(xin + base + i + ic * 4752));
            }
            if (tid < 16) {
                const int i = 1280 + tid;
                asm volatile("cp.async.cg.shared.global [%0], [%1], 16;\n"
                             :: "r"(sb + i * 16), "l"(xin + base + i + 2 * 4752));
            }
            asm volatile("cp.async.commit_group;\n");
            asm volatile("cp.async.wait_group 1;\n");   // current tile ready
        } else {
            asm volatile("cp.async.wait_group 0;\n");
        }
        __syncthreads();   // current data visible; prev pooling done (sconv safe)

        const float4* buf = patch[cur];
        const int f = tile / 12, py = tile - f * 12;

        // ---- compute phase ----
        if (tid < 108) {
            const int px = tid % 12;
            const int s9 = tid / 12;
            const int sy = s9 / 3, sx = s9 - sy * 3;

            ulonglong2 xr[12];
            #pragma unroll
            for (int ic = 0; ic < 3; ic++)
                #pragma unroll
                for (int ky = 0; ky < 4; ky++)
                    xr[ic * 4 + ky] = *(const ulonglong2*)
                        &buf[(ic * 12 + sy * 4 + ky) * 36 + px * 3 + sx];

            #pragma unroll
            for (int ch = 0; ch < 16; ch++) {
                const ulonglong2* wch = (const ulonglong2*)(swt + ch * 12);
                ull A = 0, B = 0;
                #pragma unroll
                for (int r = 0; r < 12; r++) {
                    const ulonglong2 wr = wch[r];   // broadcast (same addr)
                    A = fma2(xr[r].x, wr.x, A);
                    B = fma2(xr[r].y, wr.y, B);
                }
                const ull S = add2(A, B);
                sconv[(s9 * 12 + px) * 16 + ch] = lo2(S) + hi2(S);
            }
        }
        __syncthreads();   // sconv ready; also fences buf reads vs next issue

        // ---- pooling phase: 192 (px,ch) outputs ----
        {
            const int px = tid >> 4;
            float m = -1e30f;
            #pragma unroll
            for (int s9 = 0; s9 < 9; s9++)
                m = fmaxf(m, fmaxf(fmaf(sconv[(s9 * 12 + px) * 16 + ch_p], scale, shift2), 0.0f));
            g_y1[((f * 16 + ch_p) * 12 + py) * 12 + px] = m;
        }
        if (tid < 64) {
            const int px = (128 + tid) >> 4;
            float m = -1e30f;
            #pragma unroll
            for (int s9 = 0; s9 < 9; s9++)
                m = fmaxf(m, fmaxf(fmaf(sconv[(s9 * 12 + px) * 16 + ch_p], scale, shift2), 0.0f));
            g_y1[((f * 16 + ch_p) * 12 + py) * 12 + px] = m;
        }
    }
}

// ---------------- Kernel B: conv2 -> scalar per frame ------------------------
__global__ void __launch_bounds__(256) conv2_kernel(
    const float* __restrict__ w2, const float* __restrict__ b2p,
    const float* __restrict__ bg, const float* __restrict__ bb,
    const float* __restrict__ bm, const float* __restrict__ bv)
{
    const int f = blockIdx.x * 8 + (threadIdx.x >> 5);
    const int lane = threadIdx.x & 31;
    const int ch = lane & 15, half = lane >> 4;

    const float4* wf4 = (const float4*)w2;
    const float4 wa = wf4[ch * 4 + half * 2 + 0];
    const float4 wb = wf4[ch * 4 + half * 2 + 1];

    const float scale = bg[0] * rsqrtf(bv[0] + BEPS);
    const float shift = bb[0] - bm[0] * scale;
    const float cb = b2p[0];

    const float4* y4 = (const float4*)g_y1;
    const long cbase = ((long)f * 16 + ch) * 36;

    float best = -1e30f;
    #pragma unroll
    for (int sy = 0; sy < 3; sy++) {
        #pragma unroll
        for (int sx = 0; sx < 3; sx++) {
            int ky0 = half * 2;
            float4 va = y4[cbase + (sy * 4 + ky0) * 3 + sx];
            float4 vb = y4[cbase + (sy * 4 + ky0 + 1) * 3 + sx];
            float acc = acc4(acc4(0.0f, va, wa), vb, wb);
            #pragma unroll
            for (int off = 16; off; off >>= 1)
                acc += __shfl_xor_sync(0xffffffffu, acc, off);
            float val = fmaxf(fmaf(acc + cb, scale, shift), 0.0f);
            best = fmaxf(best, val);
        }
    }
    if (lane == 0) g_c[f] = best;
}

// ---------------- Kernel C: gating MLP + argmax + chain build ----------------
__global__ void __launch_bounds__(1024) gate_kernel(
    const float* __restrict__ w1, const float* __restrict__ b1,
    const float* __restrict__ w2, const float* __restrict__ b2,
    const float* __restrict__ w3, const float* __restrict__ b3)
{
    __shared__ float sc[32][65];
    __shared__ float sh1[32][33];
    __shared__ float sh2[32][33];
    __shared__ float sw1[2048];
    __shared__ float sw2[1024];
    const int tid = threadIdx.x;
    const int s = tid >> 5, j = tid & 31;

    for (int i = tid; i < 2048; i += 1024) {
        sc[i >> 6][i & 63] = g_c[i];
        sw1[i] = w1[i];
    }
    if (tid < 1024) sw2[tid] = w2[tid];
    __syncthreads();

    {
        float acc = b1[j];
        #pragma unroll 8
        for (int t = 0; t < 64; t++) acc = fmaf(sc[s][t], sw1[j * 64 + t], acc);
        sh1[s][j] = fast_tanh(acc);
    }
    __syncthreads();
    {
        float acc = b2[j];
        #pragma unroll
        for (int t = 0; t < 32; t++) acc = fmaf(sh1[s][t], sw2[j * 32 + t], acc);
        sh2[s][j] = fast_tanh(acc);
    }
    __syncthreads();

    if (tid < 32) {
        float bestv = -1e30f; int besti = 0;
        #pragma unroll
        for (int a = 0; a < 6; a++) {
            float acc = b3[a];
            #pragma unroll
            for (int t = 0; t < 32; t++) acc = fmaf(sh2[tid][t], w3[a * 32 + t], acc);
            if (acc > bestv) { bestv = acc; besti = a; }
        }
        g_p[tid] = besti;
    }
    __syncthreads();

    if (tid == 0) {
        int cnt[6] = {0, 0, 0, 0, 0, 0};
        for (int b = 0; b < 32; b++) {
            int e = g_p[b];
            g_chain[e][cnt[e]++] = b;
        }
        for (int e = 0; e < 6; e++) g_chain_len[e] = cnt[e];
    }
}

// ---------------- Kernel D: 4-warp per-expert LSTM + output head -------------
__global__ void __launch_bounds__(128) lstm_kernel(
    const float* __restrict__ wih,   // [6,128,1]
    const float* __restrict__ whh,   // [6,128,32]
    const float* __restrict__ bih,   // [6,128]
    const float* __restrict__ bhh,   // [6,128]
    const float* __restrict__ hn0,   // [6,32]
    const float* __restrict__ outw,  // [6,64]
    const float* __restrict__ outb,  // [6]
    float* __restrict__ out)         // [32,6]
{
    const int e = blockIdx.x;
    const int tid = threadIdx.x;
    const int w = tid >> 5;          // gate index (0=i,1=f,2=g,3=o)
    const int k = tid & 31;          // hidden unit
    const int len = g_chain_len[e];
    if (len == 0) return;

    const int row = 32 * w + k;
    ull W2[16];
    {
        const ull* wr = (const ull*)(whh + (long)e * 4096 + (long)row * 32);
        #pragma unroll
        for (int j = 0; j < 16; j++) W2[j] = wr[j];
    }
    const float wx   = wih[e * 128 + row];
    const float bsum = bih[e * 128 + row] + bhh[e * 128 + row];
    const bool  isg  = (w == 2);

    float h = hn0[e * 32 + k];

    __shared__ ull    shh[4][16];    // per-warp private h copy (pairs)
    __shared__ float4 actb[2][32];   // [buf][k] = (i,f,g,o)
    __shared__ float  scx[64];
    __shared__ float  sr[64];

    ((float*)shh[w])[k] = h;
    __syncwarp();

    for (int s = 0; s < len; s++) {
        const int b = g_chain[e][s];
        if (w == 0) {
            scx[k]      = g_c[b * 64 + k];
            scx[k + 32] = g_c[b * 64 + 32 + k];
        }
        float cst = 0.0f;
        __syncthreads();

        #pragma unroll 2
        for (int t = 0; t < 64; t++) {
            const float xt = scx[t];
            ull A0 = 0, A1 = 0, A2 = 0, A3 = 0;
            #pragma unroll
            for (int m = 0; m < 4; m++) {
                const ull h0 = shh[w][4 * m + 0];
                const ull h1 = shh[w][4 * m + 1];
                const ull h2 = shh[w][4 * m + 2];
                const ull h3 = shh[w][4 * m + 3];
                A0 = fma2(W2[4 * m + 0], h0, A0);
                A1 = fma2(W2[4 * m + 1], h1, A1);
                A2 = fma2(W2[4 * m + 2], h2, A2);
                A3 = fma2(W2[4 * m + 3], h3, A3);
            }
            const ull A = add2(add2(A0, A1), add2(A2, A3));
            const float a = (lo2(A) + hi2(A)) + fmaf(wx, xt, bsum);
            const float act = isg ? tanhap(a) : sigap(a);
            ((float*)(&actb[t & 1][k]))[w] = act;
            __syncthreads();

            const float4 g4 = actb[t & 1][k];
            cst = fmaf(g4.y, cst, g4.x * g4.z);
            h = g4.w * tanhap(cst);
            ((float*)shh[w])[k] = h;
            if (k == 31) sr[t] = h;          // all warps write same value
            __syncwarp();
        }

        if (w == 0) {
            if (k < 6) {
                float acc = outb[k];
                #pragma unroll 8
                for (int t = 0; t < 64; t++) acc = fmaf(sr[t], outw[k * 64 + t], acc);
                out[b * 6 + k] = acc;
            }
        }
    }
}

// ---------------- launch ----------------
extern "C" void kernel_launch(void* const* d_in, const int* in_sizes, int n_in,
                              void* d_out, int out_size)
{
    const float* x       = (const float*)d_in[0];
    const float* conv1_w = (const float*)d_in[1];
    const float* conv1_b = (const float*)d_in[2];
    const float* bn1_g   = (const float*)d_in[3];
    const float* bn1_b   = (const float*)d_in[4];
    const float* bn1_m   = (const float*)d_in[5];
    const float* bn1_v   = (const float*)d_in[6];
    const float* conv2_w = (const float*)d_in[7];
    const float* conv2_b = (const float*)d_in[8];
    const float* bn2_g   = (const float*)d_in[9];
    const float* bn2_b   = (const float*)d_in[10];
    const float* bn2_m   = (const float*)d_in[11];
    const float* bn2_v   = (const float*)d_in[12];
    const float* pre_w1  = (const float*)d_in[13];
    const float* pre_b1  = (const float*)d_in[14];
    const float* pre_w2  = (const float*)d_in[15];
    const float* pre_b2  = (const float*)d_in[16];
    const float* pre_w3  = (const float*)d_in[17];
    const float* pre_b3  = (const float*)d_in[18];
    const float* lstm_wih = (const float*)d_in[19];
    const float* lstm_whh = (const float*)d_in[20];
    const float* lstm_bih = (const float*)d_in[21];
    const float* lstm_bhh = (const float*)d_in[22];
    const float* hn0     = (const float*)d_in[23];
    const float* out_w   = (const float*)d_in[24];
    const float* out_b   = (const float*)d_in[25];
    float* out = (float*)d_out;

    const int c1_smem = 2784 * 16 + 6912;   // 51456 B
    cudaFuncSetAttribute(conv1_kernel,
                         cudaFuncAttributeMaxDynamicSharedMemorySize, c1_smem);

    conv1_kernel<<<C1_GRID, 128, c1_smem>>>(x, conv1_w, conv1_b, bn1_g, bn1_b, bn1_m, bn1_v);
    conv2_kernel<<<FRAMES / 8, 256>>>(conv2_w, conv2_b, bn2_g, bn2_b, bn2_m, bn2_v);
    gate_kernel<<<1, 1024>>>(pre_w1, pre_b1, pre_w2, pre_b2, pre_w3, pre_b3);
    lstm_kernel<<<6, 128>>>(lstm_wih, lstm_whh, lstm_bih, lstm_bhh, hn0, out_w, out_b, out);
}

// round 16
// speedup vs baseline: 1.1166x; 1.0014x over previous
#include <cuda_runtime.h>
#include <math.h>

#define FRAMES 2048
#define BEPS 1e-5f
#define C1_TILES (FRAMES * 12)
#define C1_GRID 444

typedef unsigned long long ull;

// ---------------- scratch ----------------
__device__ __align__(16) float g_y1[FRAMES * 16 * 144];   // [2048,16,12,12]
__device__ float g_c[FRAMES];
__device__ int   g_p[32];
__device__ int   g_chain[6][32];
__device__ int   g_chain_len[6];

__device__ __forceinline__ float fast_tanh(float x) {
    return 1.0f - 2.0f / (1.0f + __expf(2.0f * x));
}
__device__ __forceinline__ float tanhap(float x) {
    float y;
    asm("tanh.approx.f32 %0, %1;" : "=f"(y) : "f"(x));
    return y;
}
__device__ __forceinline__ float sigap(float x) {
    return fmaf(0.5f, tanhap(0.5f * x), 0.5f);
}
__device__ __forceinline__ ull fma2(ull a, ull b, ull c) {
    ull d;
    asm("fma.rn.f32x2 %0, %1, %2, %3;" : "=l"(d) : "l"(a), "l"(b), "l"(c));
    return d;
}
__device__ __forceinline__ ull add2(ull a, ull b) {
    ull d;
    asm("add.rn.f32x2 %0, %1, %2;" : "=l"(d) : "l"(a), "l"(b));
    return d;
}
__device__ __forceinline__ float lo2(ull a) { return __uint_as_float((unsigned)(a & 0xffffffffu)); }
__device__ __forceinline__ float hi2(ull a) { return __uint_as_float((unsigned)(a >> 32)); }
__device__ __forceinline__ float acc4(float acc, float4 a, float4 b) {
    acc = fmaf(a.x, b.x, acc);
    acc = fmaf(a.y, b.y, acc);
    acc = fmaf(a.z, b.z, acc);
    acc = fmaf(a.w, b.w, acc);
    return acc;
}

__device__ __forceinline__ void c1_issue_tile(const float4* __restrict__ xin,
                                              int tile, unsigned sb, int tid)
{
    const int f = tile / 12, py = tile - f * 12;
    const long base = (long)f * 15552 + (long)py * 432;
    #pragma unroll
    for (int j = 0; j < 10; j++) {
        const int i = tid + j * 128;
        const int ic = i / 432;
        asm volatile("cp.async.cg.shared.global [%0], [%1], 16;\n"
                     :: "r"(sb + i * 16), "l"(xin + base + i + ic * 4752));
    }
    if (tid < 16) {
        const int i = 1280 + tid;
        asm volatile("cp.async.cg.shared.global [%0], [%1], 16;\n"
                     :: "r"(sb + i * 16), "l"(xin + base + i + 2 * 4752));
    }
}

// ---------------- Kernel A: conv1 — persistent, 3-stage cp.async pipeline ----
// 444 CTAs x 128 threads (3 CTAs/SM); prefetch distance 2 hides full DRAM
// latency behind ~2 tile-compute periods. One (possibly empty) commit_group
// per iteration keeps wait_group 2 == "current tile arrived".
__global__ void __launch_bounds__(128) conv1_kernel(
    const float* __restrict__ x,
    const float* __restrict__ w,        // [16,3,4,4]
    const float* __restrict__ bias,
    const float* __restrict__ bg, const float* __restrict__ bb,
    const float* __restrict__ bm, const float* __restrict__ bv)
{
    extern __shared__ __align__(16) float4 dsm[];
    float4* patch[3] = { dsm, dsm + 1296, dsm + 2592 };  // 3 x 20736 B
    float4* swt = dsm + 3888;                            // 192 f4 = 3072 B
    float*  sconv = (float*)(dsm + 4080);                // 1728 floats = 6912 B

    const int tid = threadIdx.x;
    const float4* xin = (const float4*)x;

    // per-thread pooling constants (both outputs share ch = tid & 15)
    const int ch_p = tid & 15;
    const float scale = bg[ch_p] * rsqrtf(bv[ch_p] + BEPS);
    const float shift2 = bb[ch_p] - bm[ch_p] * scale + bias[ch_p] * scale;

    unsigned sb_patch[3];
    #pragma unroll
    for (int q = 0; q < 3; q++)
        sb_patch[q] = (unsigned)__cvta_generic_to_shared(patch[q]);

    int tile = blockIdx.x;
    // ---- prologue: weights + tile into patch[0] (group 1), tile+G (group 2) --
    {
        const unsigned sb_w = (unsigned)__cvta_generic_to_shared(swt);
        const float4* wg = (const float4*)w;
        asm volatile("cp.async.cg.shared.global [%0], [%1], 16;\n"
                     :: "r"(sb_w + tid * 16), "l"(wg + tid));
        if (tid < 64)
            asm volatile("cp.async.cg.shared.global [%0], [%1], 16;\n"
                         :: "r"(sb_w + (128 + tid) * 16), "l"(wg + 128 + tid));
        if (tile < C1_TILES) c1_issue_tile(xin, tile, sb_patch[0], tid);
        asm volatile("cp.async.commit_group;\n");
        if (tile + C1_GRID < C1_TILES)
            c1_issue_tile(xin, tile + C1_GRID, sb_patch[1], tid);
        asm volatile("cp.async.commit_group;\n");
    }

    int cur = 0;
    for (; tile < C1_TILES; tile += C1_GRID) {
        // ---- prefetch tile+2G into the third buffer; always commit ----
        const int nxt2 = tile + 2 * C1_GRID;
        if (nxt2 < C1_TILES) {
            const int p2 = (cur + 2 >= 3) ? cur - 1 : cur + 2;
            c1_issue_tile(xin, nxt2, sb_patch[p2], tid);
        }
        asm volatile("cp.async.commit_group;\n");
        asm volatile("cp.async.wait_group 2;\n");   // current tile ready
        __syncthreads();   // data visible; prev pooling done (sconv safe)

        const float4* buf = patch[cur];
        const int f = tile / 12, py = tile - f * 12;

        // ---- compute phase: 108 (px,sy,sx) sub-convs, all 16 channels ----
        if (tid < 108) {
            const int px = tid % 12;
            const int s9 = tid / 12;
            const int sy = s9 / 3, sx = s9 - sy * 3;

            ulonglong2 xr[12];
            #pragma unroll
            for (int ic = 0; ic < 3; ic++)
                #pragma unroll
                for (int ky = 0; ky < 4; ky++)
                    xr[ic * 4 + ky] = *(const ulonglong2*)
                        &buf[(ic * 12 + sy * 4 + ky) * 36 + px * 3 + sx];

            #pragma unroll
            for (int ch = 0; ch < 16; ch++) {
                const ulonglong2* wch = (const ulonglong2*)(swt + ch * 12);
                ull A = 0, B = 0;
                #pragma unroll
                for (int r = 0; r < 12; r++) {
                    const ulonglong2 wr = wch[r];   // broadcast (same addr)
                    A = fma2(xr[r].x, wr.x, A);
                    B = fma2(xr[r].y, wr.y, B);
                }
                const ull S = add2(A, B);
                sconv[(s9 * 12 + px) * 16 + ch] = lo2(S) + hi2(S);
            }
        }
        __syncthreads();   // sconv ready; fences buf reads vs future issues

        // ---- pooling phase: 192 (px,ch) outputs ----
        {
            const int px = tid >> 4;
            float m = -1e30f;
            #pragma unroll
            for (int s9 = 0; s9 < 9; s9++)
                m = fmaxf(m, fmaxf(fmaf(sconv[(s9 * 12 + px) * 16 + ch_p], scale, shift2), 0.0f));
            g_y1[((f * 16 + ch_p) * 12 + py) * 12 + px] = m;
        }
        if (tid < 64) {
            const int px = (128 + tid) >> 4;
            float m = -1e30f;
            #pragma unroll
            for (int s9 = 0; s9 < 9; s9++)
                m = fmaxf(m, fmaxf(fmaf(sconv[(s9 * 12 + px) * 16 + ch_p], scale, shift2), 0.0f));
            g_y1[((f * 16 + ch_p) * 12 + py) * 12 + px] = m;
        }
        cur = (cur + 1 >= 3) ? 0 : cur + 1;
    }
}

// ---------------- Kernel B: conv2 -> scalar per frame ------------------------
__global__ void __launch_bounds__(256) conv2_kernel(
    const float* __restrict__ w2, const float* __restrict__ b2p,
    const float* __restrict__ bg, const float* __restrict__ bb,
    const float* __restrict__ bm, const float* __restrict__ bv)
{
    const int f = blockIdx.x * 8 + (threadIdx.x >> 5);
    const int lane = threadIdx.x & 31;
    const int ch = lane & 15, half = lane >> 4;

    const float4* wf4 = (const float4*)w2;
    const float4 wa = wf4[ch * 4 + half * 2 + 0];
    const float4 wb = wf4[ch * 4 + half * 2 + 1];

    const float scale = bg[0] * rsqrtf(bv[0] + BEPS);
    const float shift = bb[0] - bm[0] * scale;
    const float cb = b2p[0];

    const float4* y4 = (const float4*)g_y1;
    const long cbase = ((long)f * 16 + ch) * 36;

    float best = -1e30f;
    #pragma unroll
    for (int sy = 0; sy < 3; sy++) {
        #pragma unroll
        for (int sx = 0; sx < 3; sx++) {
            int ky0 = half * 2;
            float4 va = y4[cbase + (sy * 4 + ky0) * 3 + sx];
            float4 vb = y4[cbase + (sy * 4 + ky0 + 1) * 3 + sx];
            float acc = acc4(acc4(0.0f, va, wa), vb, wb);
            #pragma unroll
            for (int off = 16; off; off >>= 1)
                acc += __shfl_xor_sync(0xffffffffu, acc, off);
            float val = fmaxf(fmaf(acc + cb, scale, shift), 0.0f);
            best = fmaxf(best, val);
        }
    }
    if (lane == 0) g_c[f] = best;
}

// ---------------- Kernel C: gating MLP + argmax + chain build ----------------
__global__ void __launch_bounds__(1024) gate_kernel(
    const float* __restrict__ w1, const float* __restrict__ b1,
    const float* __restrict__ w2, const float* __restrict__ b2,
    const float* __restrict__ w3, const float* __restrict__ b3)
{
    __shared__ float sc[32][65];
    __shared__ float sh1[32][33];
    __shared__ float sh2[32][33];
    __shared__ float sw1[2048];
    __shared__ float sw2[1024];
    const int tid = threadIdx.x;
    const int s = tid >> 5, j = tid & 31;

    for (int i = tid; i < 2048; i += 1024) {
        sc[i >> 6][i & 63] = g_c[i];
        sw1[i] = w1[i];
    }
    if (tid < 1024) sw2[tid] = w2[tid];
    __syncthreads();

    {
        float acc = b1[j];
        #pragma unroll 8
        for (int t = 0; t < 64; t++) acc = fmaf(sc[s][t], sw1[j * 64 + t], acc);
        sh1[s][j] = fast_tanh(acc);
    }
    __syncthreads();
    {
        float acc = b2[j];
        #pragma unroll
        for (int t = 0; t < 32; t++) acc = fmaf(sh1[s][t], sw2[j * 32 + t], acc);
        sh2[s][j] = fast_tanh(acc);
    }
    __syncthreads();

    if (tid < 32) {
        float bestv = -1e30f; int besti = 0;
        #pragma unroll
        for (int a = 0; a < 6; a++) {
            float acc = b3[a];
            #pragma unroll
            for (int t = 0; t < 32; t++) acc = fmaf(sh2[tid][t], w3[a * 32 + t], acc);
            if (acc > bestv) { bestv = acc; besti = a; }
        }
        g_p[tid] = besti;
    }
    __syncthreads();

    if (tid == 0) {
        int cnt[6] = {0, 0, 0, 0, 0, 0};
        for (int b = 0; b < 32; b++) {
            int e = g_p[b];
            g_chain[e][cnt[e]++] = b;
        }
        for (int e = 0; e < 6; e++) g_chain_len[e] = cnt[e];
    }
}

// ---------------- Kernel D: 4-warp per-expert LSTM + output head -------------
__global__ void __launch_bounds__(128) lstm_kernel(
    const float* __restrict__ wih,   // [6,128,1]
    const float* __restrict__ whh,   // [6,128,32]
    const float* __restrict__ bih,   // [6,128]
    const float* __restrict__ bhh,   // [6,128]
    const float* __restrict__ hn0,   // [6,32]
    const float* __restrict__ outw,  // [6,64]
    const float* __restrict__ outb,  // [6]
    float* __restrict__ out)         // [32,6]
{
    const int e = blockIdx.x;
    const int tid = threadIdx.x;
    const int w = tid >> 5;          // gate index (0=i,1=f,2=g,3=o)
    const int k = tid & 31;          // hidden unit
    const int len = g_chain_len[e];
    if (len == 0) return;

    const int row = 32 * w + k;
    ull W2[16];
    {
        const ull* wr = (const ull*)(whh + (long)e * 4096 + (long)row * 32);
        #pragma unroll
        for (int j = 0; j < 16; j++) W2[j] = wr[j];
    }
    const float wx   = wih[e * 128 + row];
    const float bsum = bih[e * 128 + row] + bhh[e * 128 + row];
    const bool  isg  = (w == 2);

    float h = hn0[e * 32 + k];

    __shared__ ull    shh[4][16];    // per-warp private h copy (pairs)
    __shared__ float4 actb[2][32];   // [buf][k] = (i,f,g,o)
    __shared__ float  scx[64];
    __shared__ float  sr[64];

    ((float*)shh[w])[k] = h;
    __syncwarp();

    for (int s = 0; s < len; s++) {
        const int b = g_chain[e][s];
        if (w == 0) {
            scx[k]      = g_c[b * 64 + k];
            scx[k + 32] = g_c[b * 64 + 32 + k];
        }
        float cst = 0.0f;
        __syncthreads();

        #pragma unroll 2
        for (int t = 0; t < 64; t++) {
            const float xt = scx[t];
            ull A0 = 0, A1 = 0, A2 = 0, A3 = 0;
            #pragma unroll
            for (int m = 0; m < 4; m++) {
                const ull h0 = shh[w][4 * m + 0];
                const ull h1 = shh[w][4 * m + 1];
                const ull h2 = shh[w][4 * m + 2];
                const ull h3 = shh[w][4 * m + 3];
                A0 = fma2(W2[4 * m + 0], h0, A0);
                A1 = fma2(W2[4 * m + 1], h1, A1);
                A2 = fma2(W2[4 * m + 2], h2, A2);
                A3 = fma2(W2[4 * m + 3], h3, A3);
            }
            const ull A = add2(add2(A0, A1), add2(A2, A3));
            const float a = (lo2(A) + hi2(A)) + fmaf(wx, xt, bsum);
            const float act = isg ? tanhap(a) : sigap(a);
            ((float*)(&actb[t & 1][k]))[w] = act;
            __syncthreads();

            const float4 g4 = actb[t & 1][k];
            cst = fmaf(g4.y, cst, g4.x * g4.z);
            h = g4.w * tanhap(cst);
            ((float*)shh[w])[k] = h;
            if (k == 31) sr[t] = h;          // all warps write same value
            __syncwarp();
        }

        if (w == 0) {
            if (k < 6) {
                float acc = outb[k];
                #pragma unroll 8
                for (int t = 0; t < 64; t++) acc = fmaf(sr[t], outw[k * 64 + t], acc);
                out[b * 6 + k] = acc;
            }
        }
    }
}

// ---------------- launch ----------------
extern "C" void kernel_launch(void* const* d_in, const int* in_sizes, int n_in,
                              void* d_out, int out_size)
{
    const float* x       = (const float*)d_in[0];
    const float* conv1_w = (const float*)d_in[1];
    const float* conv1_b = (const float*)d_in[2];
    const float* bn1_g   = (const float*)d_in[3];
    const float* bn1_b   = (const float*)d_in[4];
    const float* bn1_m   = (const float*)d_in[5];
    const float* bn1_v   = (const float*)d_in[6];
    const float* conv2_w = (const float*)d_in[7];
    const float* conv2_b = (const float*)d_in[8];
    const float* bn2_g   = (const float*)d_in[9];
    const float* bn2_b   = (const float*)d_in[10];
    const float* bn2_m   = (const float*)d_in[11];
    const float* bn2_v   = (const float*)d_in[12];
    const float* pre_w1  = (const float*)d_in[13];
    const float* pre_b1  = (const float*)d_in[14];
    const float* pre_w2  = (const float*)d_in[15];
    const float* pre_b2  = (const float*)d_in[16];
    const float* pre_w3  = (const float*)d_in[17];
    const float* pre_b3  = (const float*)d_in[18];
    const float* lstm_wih = (const float*)d_in[19];
    const float* lstm_whh = (const float*)d_in[20];
    const float* lstm_bih = (const float*)d_in[21];
    const float* lstm_bhh = (const float*)d_in[22];
    const float* hn0     = (const float*)d_in[23];
    const float* out_w   = (const float*)d_in[24];
    const float* out_b   = (const float*)d_in[25];
    float* out = (float*)d_out;

    const int c1_smem = 4080 * 16 + 6912;   // 72192 B
    cudaFuncSetAttribute(conv1_kernel,
                         cudaFuncAttributeMaxDynamicSharedMemorySize, c1_smem);

    conv1_kernel<<<C1_GRID, 128, c1_smem>>>(x, conv1_w, conv1_b, bn1_g, bn1_b, bn1_m, bn1_v);
    conv2_kernel<<<FRAMES / 8, 256>>>(conv2_w, conv2_b, bn2_g, bn2_b, bn2_m, bn2_v);
    gate_kernel<<<1, 1024>>>(pre_w1, pre_b1, pre_w2, pre_b2, pre_w3, pre_b3);
    lstm_kernel<<<6, 128>>>(lstm_wih, lstm_whh, lstm_bih, lstm_bhh, hn0, out_w, out_b, out);
}